// round 1
// baseline (speedup 1.0000x reference)
#include <cuda_runtime.h>
#include <cuda_fp16.h>
#include <cstdint>

#define BDIM 16384
#define DDIM 2048

// ---------------- device scratch (no runtime allocation allowed) ----------------
__device__ __align__(16) __half g_xh   [BDIM * DDIM];
__device__ __align__(16) __half g_wvT  [3][DDIM * DDIM];
__device__ __align__(16) __half g_woh  [3][DDIM * DDIM];
__device__ __align__(16) __half g_Mh   [3][DDIM * DDIM];     // folded branch weight  [j, d]
__device__ __align__(16) float  g_bfold[3][DDIM];
__device__ __align__(16) __half g_branch[3][BDIM * DDIM];
__device__ __align__(16) __half g_concat[(size_t)BDIM * 3 * DDIM];
__device__ __align__(16) __half g_fw1h [DDIM * 3 * DDIM];
__device__ __align__(16) __half g_fw2h [DDIM * DDIM];
__device__ __align__(16) __half g_ffw1h[4 * DDIM * DDIM];
__device__ __align__(16) __half g_ffw2h[DDIM * 4 * DDIM];
__device__ __align__(16) __half g_h1   [BDIM * DDIM];
__device__ __align__(16) __half g_fused[BDIM * DDIM];
__device__ __align__(16) __half g_h2   [(size_t)BDIM * 4 * DDIM];

// ---------------- small utility kernels ----------------

// fp32 -> fp16, 8 elements per thread (n must be multiple of 8)
__global__ void convert_kernel(const float* __restrict__ in, __half* __restrict__ out, int n8)
{
    int i = blockIdx.x * blockDim.x + threadIdx.x;
    if (i >= n8) return;
    const float4* p = (const float4*)in + 2 * (size_t)i;
    float4 a = p[0], b = p[1];
    __half2* o = (__half2*)(out + (size_t)8 * i);
    o[0] = __floats2half2_rn(a.x, a.y);
    o[1] = __floats2half2_rn(a.z, a.w);
    o[2] = __floats2half2_rn(b.x, b.y);
    o[3] = __floats2half2_rn(b.z, b.w);
}

// transpose 2048x2048 fp32 -> fp16 (out[d][k] = in[k][d])
__global__ void transpose_convert_kernel(const float* __restrict__ in, __half* __restrict__ out)
{
    __shared__ float t[32][33];
    const int bx = blockIdx.x * 32;  // input col
    const int by = blockIdx.y * 32;  // input row
    const int tx = threadIdx.x, ty = threadIdx.y;   // blockDim (32, 8)
#pragma unroll
    for (int i = 0; i < 4; ++i)
        t[ty + i * 8][tx] = in[(size_t)(by + ty + i * 8) * DDIM + bx + tx];
    __syncthreads();
#pragma unroll
    for (int i = 0; i < 4; ++i)
        out[(size_t)(bx + ty + i * 8) * DDIM + by + tx] = __float2half(t[tx][ty + i * 8]);
}

// b'[j] = bo[j] + sum_k bv[k] * wo[j][k]   (one warp per output row)
__global__ void fold_bias_kernel(const float* __restrict__ wo, const float* __restrict__ bv,
                                 const float* __restrict__ bo, float* __restrict__ out)
{
    int gw   = (blockIdx.x * blockDim.x + threadIdx.x) >> 5;
    int lane = threadIdx.x & 31;
    if (gw >= DDIM) return;
    float s = 0.f;
    for (int k = lane; k < DDIM; k += 32) s += bv[k] * wo[(size_t)gw * DDIM + k];
#pragma unroll
    for (int o = 16; o; o >>= 1) s += __shfl_xor_sync(0xffffffffu, s, o);
    if (lane == 0) out[gw] = s + bo[gw];
}

// Fused triple LayerNorm: for each row, for each branch j:
//   y = LN(x + branch_j) * g_j + b_j  -> concat[row, j*D : (j+1)*D]  (fp16)
__global__ void __launch_bounds__(256) ln3_kernel(
    const float* __restrict__ x,
    const __half* __restrict__ br0, const __half* __restrict__ br1, const __half* __restrict__ br2,
    const float* __restrict__ g0, const float* __restrict__ bb0,
    const float* __restrict__ g1, const float* __restrict__ bb1,
    const float* __restrict__ g2, const float* __restrict__ bb2,
    __half* __restrict__ concat)
{
    const int row  = blockIdx.x;
    const int tid  = threadIdx.x;
    const int c    = tid * 8;                    // 256 * 8 = 2048
    const int warp = tid >> 5, lane = tid & 31;
    __shared__ float rsum[8], rsq[8];

    float xv[8];
    {
        const float4* xp = (const float4*)(x + (size_t)row * DDIM + c);
        float4 a = xp[0], b = xp[1];
        xv[0]=a.x; xv[1]=a.y; xv[2]=a.z; xv[3]=a.w;
        xv[4]=b.x; xv[5]=b.y; xv[6]=b.z; xv[7]=b.w;
    }

    const __half* brs[3] = {br0, br1, br2};
    const float*  gs[3]  = {g0, g1, g2};
    const float*  bs[3]  = {bb0, bb1, bb2};

    for (int j = 0; j < 3; ++j) {
        float s[8];
        const __half2* bp = (const __half2*)(brs[j] + (size_t)row * DDIM + c);
#pragma unroll
        for (int q = 0; q < 4; ++q) {
            float2 f = __half22float2(bp[q]);
            s[2*q]   = xv[2*q]   + f.x;
            s[2*q+1] = xv[2*q+1] + f.y;
        }
        float sum = 0.f, sq = 0.f;
#pragma unroll
        for (int q = 0; q < 8; ++q) { sum += s[q]; sq += s[q] * s[q]; }
#pragma unroll
        for (int o = 16; o; o >>= 1) {
            sum += __shfl_xor_sync(0xffffffffu, sum, o);
            sq  += __shfl_xor_sync(0xffffffffu, sq,  o);
        }
        if (lane == 0) { rsum[warp] = sum; rsq[warp] = sq; }
        __syncthreads();
        if (tid == 0) {
            float a = 0.f, b2 = 0.f;
#pragma unroll
            for (int i = 0; i < 8; ++i) { a += rsum[i]; b2 += rsq[i]; }
            rsum[0] = a; rsq[0] = b2;
        }
        __syncthreads();
        const float mean = rsum[0] * (1.0f / DDIM);
        const float var  = rsq[0]  * (1.0f / DDIM) - mean * mean;
        const float inv  = rsqrtf(var + 1e-5f);

        __half2* op = (__half2*)(concat + (size_t)row * (3 * DDIM) + (size_t)j * DDIM + c);
#pragma unroll
        for (int q = 0; q < 4; ++q) {
            float gA = gs[j][c + 2*q],     gB = gs[j][c + 2*q + 1];
            float bA = bs[j][c + 2*q],     bB = bs[j][c + 2*q + 1];
            op[q] = __floats2half2_rn((s[2*q]   - mean) * inv * gA + bA,
                                      (s[2*q+1] - mean) * inv * gB + bB);
        }
        __syncthreads();   // protect rsum/rsq before next branch
    }
}

// ---------------- GEMM: C[M,N] = sum_k A[m,k] * B[n,k]  (A,B fp16 row-major, fp32 accum) ----------------
#define GBM 128
#define GBN 128
#define GBK 32
#define SST 40   // BK + 8 halves pad -> conflict-free ldmatrix

#define CPA16(dst, src) asm volatile("cp.async.cg.shared.global [%0], [%1], 16;" :: "r"(dst), "l"(src))

enum { EPI_HB = 0, EPI_HBR = 1, EPI_H = 2, EPI_FINAL = 3 };

template<int EPI>
__global__ void __launch_bounds__(256)
gemm_nt(const __half* __restrict__ A, const __half* __restrict__ Bm,
        const float* __restrict__ bias,
        const float* __restrict__ addX, const __half* __restrict__ addF,
        void* __restrict__ Cout, int M, int N, int K)
{
    __shared__ __half sA[2][GBM * SST];
    __shared__ __half sB[2][GBN * SST];

    const int tid  = threadIdx.x;
    const int lane = tid & 31;
    const int warp = tid >> 5;
    const int wm = warp >> 2;     // 0..1
    const int wn = warp & 3;      // 0..3
    const int bm0 = blockIdx.y * GBM;
    const int bn0 = blockIdx.x * GBN;

    // cp.async mapping: chunk id = tid (+256); row = id/4, 16B chunk = id%4
    const int r0 = tid >> 2;
    const int c0 = (tid & 3) << 3;

    const __half* Ag0 = A + (size_t)(bm0 + r0) * K + c0;
    const __half* Ag1 = Ag0 + (size_t)64 * K;
    const __half* Bg0 = Bm + (size_t)(bn0 + r0) * K + c0;
    const __half* Bg1 = Bg0 + (size_t)64 * K;

    uint32_t sAb[2], sBb[2];
    sAb[0] = (uint32_t)__cvta_generic_to_shared(&sA[0][0]);
    sAb[1] = (uint32_t)__cvta_generic_to_shared(&sA[1][0]);
    sBb[0] = (uint32_t)__cvta_generic_to_shared(&sB[0][0]);
    sBb[1] = (uint32_t)__cvta_generic_to_shared(&sB[1][0]);

    const uint32_t so0 = (uint32_t)(r0 * SST + c0) * 2u;
    const uint32_t so1 = (uint32_t)((r0 + 64) * SST + c0) * 2u;

    const int KT = K / GBK;

    // prologue: tile 0 -> buf 0
    CPA16(sAb[0] + so0, Ag0);
    CPA16(sAb[0] + so1, Ag1);
    CPA16(sBb[0] + so0, Bg0);
    CPA16(sBb[0] + so1, Bg1);
    asm volatile("cp.async.commit_group;");

    float acc[4][4][4];
#pragma unroll
    for (int a = 0; a < 4; ++a)
#pragma unroll
        for (int b = 0; b < 4; ++b)
#pragma unroll
            for (int q = 0; q < 4; ++q) acc[a][b][q] = 0.f;

    const int lrow = lane & 15;
    const int lcol = (lane >> 4) << 3;

    for (int kt = 0; kt < KT; ++kt) {
        const int buf = kt & 1;
        if (kt + 1 < KT) {
            const int koff = (kt + 1) * GBK;
            CPA16(sAb[buf ^ 1] + so0, Ag0 + koff);
            CPA16(sAb[buf ^ 1] + so1, Ag1 + koff);
            CPA16(sBb[buf ^ 1] + so0, Bg0 + koff);
            CPA16(sBb[buf ^ 1] + so1, Bg1 + koff);
            asm volatile("cp.async.commit_group;");
            asm volatile("cp.async.wait_group 1;");
        } else {
            asm volatile("cp.async.wait_group 0;");
        }
        __syncthreads();

#pragma unroll
        for (int ks = 0; ks < 2; ++ks) {
            uint32_t af[4][4], bf[4][2];
            const int kcol = ks * 16 + lcol;
#pragma unroll
            for (int mt = 0; mt < 4; ++mt) {
                uint32_t addr = sAb[buf] + (uint32_t)(((wm * 64 + mt * 16 + lrow) * SST + kcol) * 2);
                asm volatile("ldmatrix.sync.aligned.m8n8.x4.shared.b16 {%0,%1,%2,%3}, [%4];"
                             : "=r"(af[mt][0]), "=r"(af[mt][1]), "=r"(af[mt][2]), "=r"(af[mt][3])
                             : "r"(addr));
            }
#pragma unroll
            for (int nt2 = 0; nt2 < 2; ++nt2) {
                uint32_t q0, q1, q2, q3;
                uint32_t addr = sBb[buf] + (uint32_t)(((wn * 32 + nt2 * 16 + lrow) * SST + kcol) * 2);
                asm volatile("ldmatrix.sync.aligned.m8n8.x4.shared.b16 {%0,%1,%2,%3}, [%4];"
                             : "=r"(q0), "=r"(q1), "=r"(q2), "=r"(q3) : "r"(addr));
                bf[nt2 * 2 + 0][0] = q0; bf[nt2 * 2 + 0][1] = q2;
                bf[nt2 * 2 + 1][0] = q1; bf[nt2 * 2 + 1][1] = q3;
            }
#pragma unroll
            for (int mt = 0; mt < 4; ++mt)
#pragma unroll
                for (int nt = 0; nt < 4; ++nt)
                    asm volatile("mma.sync.aligned.m16n8k16.row.col.f32.f16.f16.f32 "
                                 "{%0,%1,%2,%3}, {%4,%5,%6,%7}, {%8,%9}, {%0,%1,%2,%3};"
                                 : "+f"(acc[mt][nt][0]), "+f"(acc[mt][nt][1]),
                                   "+f"(acc[mt][nt][2]), "+f"(acc[mt][nt][3])
                                 : "r"(af[mt][0]), "r"(af[mt][1]), "r"(af[mt][2]), "r"(af[mt][3]),
                                   "r"(bf[nt][0]), "r"(bf[nt][1]));
        }
        __syncthreads();
    }

    // epilogue
#pragma unroll
    for (int mt = 0; mt < 4; ++mt) {
        const int mrow = bm0 + wm * 64 + mt * 16 + (lane >> 2);
#pragma unroll
        for (int nt = 0; nt < 4; ++nt) {
            const int ncol = bn0 + wn * 32 + nt * 8 + ((lane & 3) << 1);
            float v0 = acc[mt][nt][0], v1 = acc[mt][nt][1];
            float v2 = acc[mt][nt][2], v3 = acc[mt][nt][3];
            if (EPI != EPI_H) {
                float b0 = bias[ncol], b1 = bias[ncol + 1];
                v0 += b0; v1 += b1; v2 += b0; v3 += b1;
            }
            if (EPI == EPI_HBR) {
                v0 = fmaxf(v0, 0.f); v1 = fmaxf(v1, 0.f);
                v2 = fmaxf(v2, 0.f); v3 = fmaxf(v3, 0.f);
            }
            const size_t i0 = (size_t)mrow * N + ncol;
            const size_t i1 = (size_t)(mrow + 8) * N + ncol;
            if (EPI == EPI_FINAL) {
                float* O = (float*)Cout;
                float2 x0 = *(const float2*)(addX + i0);
                float2 x1 = *(const float2*)(addX + i1);
                float2 f0 = __half22float2(*(const __half2*)(addF + i0));
                float2 f1 = __half22float2(*(const __half2*)(addF + i1));
                *(float2*)(O + i0) = make_float2(v0 + x0.x + f0.x, v1 + x0.y + f0.y);
                *(float2*)(O + i1) = make_float2(v2 + x1.x + f1.x, v3 + x1.y + f1.y);
            } else {
                __half* O = (__half*)Cout;
                *(__half2*)(O + i0) = __floats2half2_rn(v0, v1);
                *(__half2*)(O + i1) = __floats2half2_rn(v2, v3);
            }
        }
    }
}

// ---------------- launcher ----------------
extern "C" void kernel_launch(void* const* d_in, const int* in_sizes, int n_in,
                              void* d_out, int out_size)
{
    (void)in_sizes; (void)n_in; (void)out_size;
    const float* x     = (const float*)d_in[0];
    const float* wv[3] = {(const float*)d_in[1], (const float*)d_in[5], (const float*)d_in[9]};
    const float* bv[3] = {(const float*)d_in[2], (const float*)d_in[6], (const float*)d_in[10]};
    const float* wo[3] = {(const float*)d_in[3], (const float*)d_in[7], (const float*)d_in[11]};
    const float* bo[3] = {(const float*)d_in[4], (const float*)d_in[8], (const float*)d_in[12]};
    const float* g[3]  = {(const float*)d_in[13], (const float*)d_in[15], (const float*)d_in[17]};
    const float* bb[3] = {(const float*)d_in[14], (const float*)d_in[16], (const float*)d_in[18]};
    const float* fw1  = (const float*)d_in[19]; const float* fb1  = (const float*)d_in[20];
    const float* fw2  = (const float*)d_in[21]; const float* fb2  = (const float*)d_in[22];
    const float* ffw1 = (const float*)d_in[23]; const float* ffb1 = (const float*)d_in[24];
    const float* ffw2 = (const float*)d_in[25]; const float* ffb2 = (const float*)d_in[26];

    void *p;
    __half *xh, *wvT, *woh, *Mh, *branch, *concat, *fw1h, *fw2h, *ffw1h, *ffw2h, *h1, *fused, *h2;
    float *bfold;
    cudaGetSymbolAddress(&p, g_xh);     xh     = (__half*)p;
    cudaGetSymbolAddress(&p, g_wvT);    wvT    = (__half*)p;
    cudaGetSymbolAddress(&p, g_woh);    woh    = (__half*)p;
    cudaGetSymbolAddress(&p, g_Mh);     Mh     = (__half*)p;
    cudaGetSymbolAddress(&p, g_bfold);  bfold  = (float*)p;
    cudaGetSymbolAddress(&p, g_branch); branch = (__half*)p;
    cudaGetSymbolAddress(&p, g_concat); concat = (__half*)p;
    cudaGetSymbolAddress(&p, g_fw1h);   fw1h   = (__half*)p;
    cudaGetSymbolAddress(&p, g_fw2h);   fw2h   = (__half*)p;
    cudaGetSymbolAddress(&p, g_ffw1h);  ffw1h  = (__half*)p;
    cudaGetSymbolAddress(&p, g_ffw2h);  ffw2h  = (__half*)p;
    cudaGetSymbolAddress(&p, g_h1);     h1     = (__half*)p;
    cudaGetSymbolAddress(&p, g_fused);  fused  = (__half*)p;
    cudaGetSymbolAddress(&p, g_h2);     h2     = (__half*)p;

    const int D  = DDIM;
    const int Bn = BDIM;
    const size_t DD = (size_t)D * D;

    // 1) convert x
    {
        int n8 = Bn * D / 8;
        convert_kernel<<<(n8 + 255) / 256, 256>>>(x, xh, n8);
    }
    // 2) per-branch weight prep
    dim3 tb(32, 8), tg(D / 32, D / 32);
    for (int k = 0; k < 3; ++k) {
        transpose_convert_kernel<<<tg, tb>>>(wv[k], wvT + k * DD);
        int n8 = (int)(DD / 8);
        convert_kernel<<<(n8 + 255) / 256, 256>>>(wo[k], woh + k * DD, n8);
        fold_bias_kernel<<<(D * 32 + 255) / 256, 256>>>(wo[k], bv[k], bo[k], bfold + k * D);
    }
    // 3) convert fusion/FFN weights
    {
        int n8 = D * 3 * D / 8;  convert_kernel<<<(n8 + 255) / 256, 256>>>(fw1,  fw1h,  n8);
        n8 = (int)(DD / 8);      convert_kernel<<<(n8 + 255) / 256, 256>>>(fw2,  fw2h,  n8);
        n8 = 4 * D * D / 8;      convert_kernel<<<(n8 + 255) / 256, 256>>>(ffw1, ffw1h, n8);
        n8 = D * 4 * D / 8;      convert_kernel<<<(n8 + 255) / 256, 256>>>(ffw2, ffw2h, n8);
    }
    // 4) folded branch weights: M_k[j,d] = sum_t Wo[j,t] * Wv[t,d]
    for (int k = 0; k < 3; ++k)
        gemm_nt<EPI_H><<<dim3(D / GBN, D / GBM), 256>>>(
            woh + k * DD, wvT + k * DD, nullptr, nullptr, nullptr,
            (void*)(Mh + k * DD), D, D, D);
    // 5) branches: branch_k = xh @ M_k^T + b'_k
    for (int k = 0; k < 3; ++k)
        gemm_nt<EPI_HB><<<dim3(D / GBN, Bn / GBM), 256>>>(
            xh, Mh + k * DD, bfold + k * D, nullptr, nullptr,
            (void*)(branch + (size_t)k * Bn * D), Bn, D, D);
    // 6) fused triple LayerNorm -> concat [B, 3D] fp16
    ln3_kernel<<<Bn, 256>>>(x,
        branch, branch + (size_t)Bn * D, branch + (size_t)2 * Bn * D,
        g[0], bb[0], g[1], bb[1], g[2], bb[2], concat);
    // 7) h1 = relu(concat @ fw1^T + fb1)
    gemm_nt<EPI_HBR><<<dim3(D / GBN, Bn / GBM), 256>>>(
        concat, fw1h, fb1, nullptr, nullptr, (void*)h1, Bn, D, 3 * D);
    // 8) fused = h1 @ fw2^T + fb2
    gemm_nt<EPI_HB><<<dim3(D / GBN, Bn / GBM), 256>>>(
        h1, fw2h, fb2, nullptr, nullptr, (void*)fused, Bn, D, D);
    // 9) h2 = relu(fused @ ffw1^T + ffb1)
    gemm_nt<EPI_HBR><<<dim3(4 * D / GBN, Bn / GBM), 256>>>(
        fused, ffw1h, ffb1, nullptr, nullptr, (void*)h2, Bn, 4 * D, D);
    // 10) out = x + fused + (h2 @ ffw2^T + ffb2)
    gemm_nt<EPI_FINAL><<<dim3(D / GBN, Bn / GBM), 256>>>(
        h2, ffw2h, ffb2, x, fused, d_out, Bn, D, 4 * D);
}

// round 3
// speedup vs baseline: 1.0387x; 1.0387x over previous
#include <cuda_runtime.h>
#include <cuda_fp16.h>
#include <cstdint>

#define BDIM 16384
#define DDIM 2048

// ---------------- device scratch ----------------
__device__ __align__(16) __half g_xh   [BDIM * DDIM];
__device__ __align__(16) __half g_wvT  [3][DDIM * DDIM];
__device__ __align__(16) __half g_woh  [3][DDIM * DDIM];
__device__ __align__(16) __half g_Mh   [3][DDIM * DDIM];     // folded weights, contiguous = [6144, 2048]
__device__ __align__(16) float  g_bfold[3][DDIM];            // contiguous = [6144]
__device__ __align__(16) __half g_branch[(size_t)BDIM * 3 * DDIM];   // [B, 6144]
__device__ __align__(16) __half g_concat[(size_t)BDIM * 3 * DDIM];
__device__ __align__(16) __half g_fw1h [DDIM * 3 * DDIM];
__device__ __align__(16) __half g_fw2h [DDIM * DDIM];
__device__ __align__(16) __half g_ffw1h[4 * DDIM * DDIM];
__device__ __align__(16) __half g_ffw2h[DDIM * 4 * DDIM];
__device__ __align__(16) __half g_h1   [BDIM * DDIM];
__device__ __align__(16) __half g_fused[BDIM * DDIM];
__device__ __align__(16) __half g_h2   [(size_t)BDIM * 4 * DDIM];

// ---------------- small utility kernels ----------------

__global__ void convert_kernel(const float* __restrict__ in, __half* __restrict__ out, int n8)
{
    int i = blockIdx.x * blockDim.x + threadIdx.x;
    if (i >= n8) return;
    const float4* p = (const float4*)in + 2 * (size_t)i;
    float4 a = p[0], b = p[1];
    __half2* o = (__half2*)(out + (size_t)8 * i);
    o[0] = __floats2half2_rn(a.x, a.y);
    o[1] = __floats2half2_rn(a.z, a.w);
    o[2] = __floats2half2_rn(b.x, b.y);
    o[3] = __floats2half2_rn(b.z, b.w);
}

__global__ void transpose_convert_kernel(const float* __restrict__ in, __half* __restrict__ out)
{
    __shared__ float t[32][33];
    const int bx = blockIdx.x * 32;
    const int by = blockIdx.y * 32;
    const int tx = threadIdx.x, ty = threadIdx.y;   // blockDim (32, 8)
#pragma unroll
    for (int i = 0; i < 4; ++i)
        t[ty + i * 8][tx] = in[(size_t)(by + ty + i * 8) * DDIM + bx + tx];
    __syncthreads();
#pragma unroll
    for (int i = 0; i < 4; ++i)
        out[(size_t)(bx + ty + i * 8) * DDIM + by + tx] = __float2half(t[tx][ty + i * 8]);
}

__global__ void fold_bias_kernel(const float* __restrict__ wo, const float* __restrict__ bv,
                                 const float* __restrict__ bo, float* __restrict__ out)
{
    int gw   = (blockIdx.x * blockDim.x + threadIdx.x) >> 5;
    int lane = threadIdx.x & 31;
    if (gw >= DDIM) return;
    float s = 0.f;
    for (int k = lane; k < DDIM; k += 32) s += bv[k] * wo[(size_t)gw * DDIM + k];
#pragma unroll
    for (int o = 16; o; o >>= 1) s += __shfl_xor_sync(0xffffffffu, s, o);
    if (lane == 0) out[gw] = s + bo[gw];
}

// branch buffer is [B, 6144]; branch k at column offset k*2048
__global__ void __launch_bounds__(256) ln3_kernel(
    const float* __restrict__ x,
    const __half* __restrict__ brc,
    const float* __restrict__ g0, const float* __restrict__ bb0,
    const float* __restrict__ g1, const float* __restrict__ bb1,
    const float* __restrict__ g2, const float* __restrict__ bb2,
    __half* __restrict__ concat)
{
    const int row  = blockIdx.x;
    const int tid  = threadIdx.x;
    const int c    = tid * 8;
    const int warp = tid >> 5, lane = tid & 31;
    __shared__ float rsum[8], rsq[8];

    float xv[8];
    {
        const float4* xp = (const float4*)(x + (size_t)row * DDIM + c);
        float4 a = xp[0], b = xp[1];
        xv[0]=a.x; xv[1]=a.y; xv[2]=a.z; xv[3]=a.w;
        xv[4]=b.x; xv[5]=b.y; xv[6]=b.z; xv[7]=b.w;
    }

    const float* gs[3] = {g0, g1, g2};
    const float* bs[3] = {bb0, bb1, bb2};

    for (int j = 0; j < 3; ++j) {
        float s[8];
        const __half2* bp = (const __half2*)(brc + (size_t)row * (3 * DDIM) + (size_t)j * DDIM + c);
#pragma unroll
        for (int q = 0; q < 4; ++q) {
            float2 f = __half22float2(bp[q]);
            s[2*q]   = xv[2*q]   + f.x;
            s[2*q+1] = xv[2*q+1] + f.y;
        }
        float sum = 0.f, sq = 0.f;
#pragma unroll
        for (int q = 0; q < 8; ++q) { sum += s[q]; sq += s[q] * s[q]; }
#pragma unroll
        for (int o = 16; o; o >>= 1) {
            sum += __shfl_xor_sync(0xffffffffu, sum, o);
            sq  += __shfl_xor_sync(0xffffffffu, sq,  o);
        }
        if (lane == 0) { rsum[warp] = sum; rsq[warp] = sq; }
        __syncthreads();
        if (tid == 0) {
            float a = 0.f, b2 = 0.f;
#pragma unroll
            for (int i = 0; i < 8; ++i) { a += rsum[i]; b2 += rsq[i]; }
            rsum[0] = a; rsq[0] = b2;
        }
        __syncthreads();
        const float mean = rsum[0] * (1.0f / DDIM);
        const float var  = rsq[0]  * (1.0f / DDIM) - mean * mean;
        const float inv  = rsqrtf(var + 1e-5f);

        __half2* op = (__half2*)(concat + (size_t)row * (3 * DDIM) + (size_t)j * DDIM + c);
#pragma unroll
        for (int q = 0; q < 4; ++q) {
            float gA = gs[j][c + 2*q],     gB = gs[j][c + 2*q + 1];
            float bA = bs[j][c + 2*q],     bB = bs[j][c + 2*q + 1];
            op[q] = __floats2half2_rn((s[2*q]   - mean) * inv * gA + bA,
                                      (s[2*q+1] - mean) * inv * gB + bB);
        }
        __syncthreads();
    }
}

// ---------------- GEMM: C[M,N] = sum_k A[m,k]*B[n,k], fp16 in, fp32 acc ----------------
// 128x128 block, 8 warps (64x32 each), 3-stage cp.async pipeline, 1 sync/tile.
#define GBM 128
#define GBN 128
#define GBK 32
#define SST 40                 // 32 + 8 halves pad
#define STAGE_H (GBM * SST)    // halves per tile buffer (A or B)
#define SMEM_GEMM (6 * STAGE_H * 2)   // 3 stages * (A+B) * 2 bytes = 61440

#define CPA16(dst, src) asm volatile("cp.async.cg.shared.global [%0], [%1], 16;" :: "r"(dst), "l"(src))

enum { EPI_HB = 0, EPI_HBR = 1, EPI_H = 2, EPI_FINAL = 3 };

template<int EPI>
__global__ void __launch_bounds__(256, 2)
gemm_nt(const __half* __restrict__ A, const __half* __restrict__ Bm,
        const float* __restrict__ bias,
        const float* __restrict__ addX, const __half* __restrict__ addF,
        void* __restrict__ Cout, int M, int N, int K,
        size_t zsA, size_t zsB, size_t zsC)
{
    extern __shared__ __align__(16) __half smem[];
    // layout: [A0 B0 A1 B1 A2 B2], each STAGE_H halves
    const int tid  = threadIdx.x;
    const int lane = tid & 31;
    const int warp = tid >> 5;
    const int wm = warp >> 2;
    const int wn = warp & 3;
    const int bm0 = blockIdx.y * GBM;
    const int bn0 = blockIdx.x * GBN;

    A  += zsA * blockIdx.z;
    Bm += zsB * blockIdx.z;

    // cp.async mapping: 512 16B-chunks per (A or B) tile; 2 per thread each
    const int r0 = tid >> 2;            // row 0..63
    const int c0 = (tid & 3) << 3;      // halves col

    const __half* Ag0 = A + (size_t)(bm0 + r0) * K + c0;
    const __half* Ag1 = Ag0 + (size_t)64 * K;
    const __half* Bg0 = Bm + (size_t)(bn0 + r0) * K + c0;
    const __half* Bg1 = Bg0 + (size_t)64 * K;

    const uint32_t sbase = (uint32_t)__cvta_generic_to_shared(smem);
    uint32_t sA[3], sB[3];
#pragma unroll
    for (int s = 0; s < 3; ++s) {
        sA[s] = sbase + (uint32_t)(2 * s)     * STAGE_H * 2;
        sB[s] = sbase + (uint32_t)(2 * s + 1) * STAGE_H * 2;
    }
    const uint32_t so0 = (uint32_t)(r0 * SST + c0) * 2u;
    const uint32_t so1 = (uint32_t)((r0 + 64) * SST + c0) * 2u;

    const int KT = K / GBK;

    // prologue: stages 0,1
#pragma unroll
    for (int s = 0; s < 2; ++s) {
        const int koff = s * GBK;
        CPA16(sA[s] + so0, Ag0 + koff);
        CPA16(sA[s] + so1, Ag1 + koff);
        CPA16(sB[s] + so0, Bg0 + koff);
        CPA16(sB[s] + so1, Bg1 + koff);
        asm volatile("cp.async.commit_group;");
    }

    float acc[4][4][4];
#pragma unroll
    for (int a = 0; a < 4; ++a)
#pragma unroll
        for (int b = 0; b < 4; ++b)
#pragma unroll
            for (int q = 0; q < 4; ++q) acc[a][b][q] = 0.f;

    const int lrow = lane & 15;
    const int lcol = (lane >> 4) << 3;

    int st = 0;
    for (int kt = 0; kt < KT; ++kt) {
        // 1) wait for this tile's data
        if (kt + 1 < KT) asm volatile("cp.async.wait_group 1;");
        else             asm volatile("cp.async.wait_group 0;");
        // 2) all warps done reading stage (kt-1)%3, and tile kt visible everywhere
        __syncthreads();
        // 3) refill stage (kt+2)%3
        if (kt + 2 < KT) {
            const int sn = (st + 2 >= 3) ? st - 1 : st + 2;
            const int koff = (kt + 2) * GBK;
            CPA16(sA[sn] + so0, Ag0 + koff);
            CPA16(sA[sn] + so1, Ag1 + koff);
            CPA16(sB[sn] + so0, Bg0 + koff);
            CPA16(sB[sn] + so1, Bg1 + koff);
            asm volatile("cp.async.commit_group;");
        }
        // 4) compute on stage st
#pragma unroll
        for (int ks = 0; ks < 2; ++ks) {
            uint32_t af[4][4], bf[4][2];
            const int kcol = ks * 16 + lcol;
#pragma unroll
            for (int mt = 0; mt < 4; ++mt) {
                uint32_t addr = sA[st] + (uint32_t)(((wm * 64 + mt * 16 + lrow) * SST + kcol) * 2);
                asm volatile("ldmatrix.sync.aligned.m8n8.x4.shared.b16 {%0,%1,%2,%3}, [%4];"
                             : "=r"(af[mt][0]), "=r"(af[mt][1]), "=r"(af[mt][2]), "=r"(af[mt][3])
                             : "r"(addr));
            }
#pragma unroll
            for (int nt2 = 0; nt2 < 2; ++nt2) {
                uint32_t q0, q1, q2, q3;
                uint32_t addr = sB[st] + (uint32_t)(((wn * 32 + nt2 * 16 + lrow) * SST + kcol) * 2);
                asm volatile("ldmatrix.sync.aligned.m8n8.x4.shared.b16 {%0,%1,%2,%3}, [%4];"
                             : "=r"(q0), "=r"(q1), "=r"(q2), "=r"(q3) : "r"(addr));
                bf[nt2 * 2 + 0][0] = q0; bf[nt2 * 2 + 0][1] = q2;
                bf[nt2 * 2 + 1][0] = q1; bf[nt2 * 2 + 1][1] = q3;
            }
#pragma unroll
            for (int mt = 0; mt < 4; ++mt)
#pragma unroll
                for (int nt = 0; nt < 4; ++nt)
                    asm volatile("mma.sync.aligned.m16n8k16.row.col.f32.f16.f16.f32 "
                                 "{%0,%1,%2,%3}, {%4,%5,%6,%7}, {%8,%9}, {%0,%1,%2,%3};"
                                 : "+f"(acc[mt][nt][0]), "+f"(acc[mt][nt][1]),
                                   "+f"(acc[mt][nt][2]), "+f"(acc[mt][nt][3])
                                 : "r"(af[mt][0]), "r"(af[mt][1]), "r"(af[mt][2]), "r"(af[mt][3]),
                                   "r"(bf[nt][0]), "r"(bf[nt][1]));
        }
        st = (st + 1 >= 3) ? 0 : st + 1;
    }

    // epilogue
    char* Cz = (char*)Cout + (EPI == EPI_FINAL ? 0 : (size_t)0) ;
    (void)Cz;
#pragma unroll
    for (int mt = 0; mt < 4; ++mt) {
        const int mrow = bm0 + wm * 64 + mt * 16 + (lane >> 2);
#pragma unroll
        for (int nt = 0; nt < 4; ++nt) {
            const int ncol = bn0 + wn * 32 + nt * 8 + ((lane & 3) << 1);
            float v0 = acc[mt][nt][0], v1 = acc[mt][nt][1];
            float v2 = acc[mt][nt][2], v3 = acc[mt][nt][3];
            if (EPI != EPI_H) {
                float b0 = bias[ncol], b1 = bias[ncol + 1];
                v0 += b0; v1 += b1; v2 += b0; v3 += b1;
            }
            if (EPI == EPI_HBR) {
                v0 = fmaxf(v0, 0.f); v1 = fmaxf(v1, 0.f);
                v2 = fmaxf(v2, 0.f); v3 = fmaxf(v3, 0.f);
            }
            const size_t i0 = (size_t)mrow * N + ncol;
            const size_t i1 = (size_t)(mrow + 8) * N + ncol;
            if (EPI == EPI_FINAL) {
                float* O = (float*)Cout;
                float2 x0 = *(const float2*)(addX + i0);
                float2 x1 = *(const float2*)(addX + i1);
                float2 f0 = __half22float2(*(const __half2*)(addF + i0));
                float2 f1 = __half22float2(*(const __half2*)(addF + i1));
                *(float2*)(O + i0) = make_float2(v0 + x0.x + f0.x, v1 + x0.y + f0.y);
                *(float2*)(O + i1) = make_float2(v2 + x1.x + f1.x, v3 + x1.y + f1.y);
            } else {
                __half* O = (__half*)Cout + zsC * blockIdx.z;
                *(__half2*)(O + i0) = __floats2half2_rn(v0, v1);
                *(__half2*)(O + i1) = __floats2half2_rn(v2, v3);
            }
        }
    }
}

// ---------------- launcher ----------------
extern "C" void kernel_launch(void* const* d_in, const int* in_sizes, int n_in,
                              void* d_out, int out_size)
{
    (void)in_sizes; (void)n_in; (void)out_size;
    const float* x     = (const float*)d_in[0];
    const float* wv[3] = {(const float*)d_in[1], (const float*)d_in[5], (const float*)d_in[9]};
    const float* bv[3] = {(const float*)d_in[2], (const float*)d_in[6], (const float*)d_in[10]};
    const float* wo[3] = {(const float*)d_in[3], (const float*)d_in[7], (const float*)d_in[11]};
    const float* bo[3] = {(const float*)d_in[4], (const float*)d_in[8], (const float*)d_in[12]};
    const float* g[3]  = {(const float*)d_in[13], (const float*)d_in[15], (const float*)d_in[17]};
    const float* bb[3] = {(const float*)d_in[14], (const float*)d_in[16], (const float*)d_in[18]};
    const float* fw1  = (const float*)d_in[19]; const float* fb1  = (const float*)d_in[20];
    const float* fw2  = (const float*)d_in[21]; const float* fb2  = (const float*)d_in[22];
    const float* ffw1 = (const float*)d_in[23]; const float* ffb1 = (const float*)d_in[24];
    const float* ffw2 = (const float*)d_in[25]; const float* ffb2 = (const float*)d_in[26];

    void *p;
    __half *xh, *wvT, *woh, *Mh, *branch, *concat, *fw1h, *fw2h, *ffw1h, *ffw2h, *h1, *fused, *h2;
    float *bfold;
    cudaGetSymbolAddress(&p, g_xh);     xh     = (__half*)p;
    cudaGetSymbolAddress(&p, g_wvT);    wvT    = (__half*)p;
    cudaGetSymbolAddress(&p, g_woh);    woh    = (__half*)p;
    cudaGetSymbolAddress(&p, g_Mh);     Mh     = (__half*)p;
    cudaGetSymbolAddress(&p, g_bfold);  bfold  = (float*)p;
    cudaGetSymbolAddress(&p, g_branch); branch = (__half*)p;
    cudaGetSymbolAddress(&p, g_concat); concat = (__half*)p;
    cudaGetSymbolAddress(&p, g_fw1h);   fw1h   = (__half*)p;
    cudaGetSymbolAddress(&p, g_fw2h);   fw2h   = (__half*)p;
    cudaGetSymbolAddress(&p, g_ffw1h);  ffw1h  = (__half*)p;
    cudaGetSymbolAddress(&p, g_ffw2h);  ffw2h  = (__half*)p;
    cudaGetSymbolAddress(&p, g_h1);     h1     = (__half*)p;
    cudaGetSymbolAddress(&p, g_fused);  fused  = (__half*)p;
    cudaGetSymbolAddress(&p, g_h2);     h2     = (__half*)p;

    cudaFuncSetAttribute(gemm_nt<EPI_HB>,    cudaFuncAttributeMaxDynamicSharedMemorySize, SMEM_GEMM);
    cudaFuncSetAttribute(gemm_nt<EPI_HBR>,   cudaFuncAttributeMaxDynamicSharedMemorySize, SMEM_GEMM);
    cudaFuncSetAttribute(gemm_nt<EPI_H>,     cudaFuncAttributeMaxDynamicSharedMemorySize, SMEM_GEMM);
    cudaFuncSetAttribute(gemm_nt<EPI_FINAL>, cudaFuncAttributeMaxDynamicSharedMemorySize, SMEM_GEMM);

    const int D  = DDIM;
    const int Bn = BDIM;
    const size_t DD = (size_t)D * D;

    // 1) convert x
    {
        int n8 = Bn * D / 8;
        convert_kernel<<<(n8 + 255) / 256, 256>>>(x, xh, n8);
    }
    // 2) per-branch weight prep
    dim3 tb(32, 8), tg(D / 32, D / 32);
    for (int k = 0; k < 3; ++k) {
        transpose_convert_kernel<<<tg, tb>>>(wv[k], wvT + k * DD);
        int n8 = (int)(DD / 8);
        convert_kernel<<<(n8 + 255) / 256, 256>>>(wo[k], woh + k * DD, n8);
        fold_bias_kernel<<<(D * 32 + 255) / 256, 256>>>(wo[k], bv[k], bo[k], bfold + k * D);
    }
    // 3) convert fusion/FFN weights
    {
        int n8 = D * 3 * D / 8;  convert_kernel<<<(n8 + 255) / 256, 256>>>(fw1,  fw1h,  n8);
        n8 = (int)(DD / 8);      convert_kernel<<<(n8 + 255) / 256, 256>>>(fw2,  fw2h,  n8);
        n8 = 4 * D * D / 8;      convert_kernel<<<(n8 + 255) / 256, 256>>>(ffw1, ffw1h, n8);
        n8 = D * 4 * D / 8;      convert_kernel<<<(n8 + 255) / 256, 256>>>(ffw2, ffw2h, n8);
    }
    // 4) folded weights, batched over z: M_k = woh_k @ wvT_k^T
    gemm_nt<EPI_H><<<dim3(D / GBN, D / GBM, 3), 256, SMEM_GEMM>>>(
        woh, wvT, nullptr, nullptr, nullptr, (void*)Mh, D, D, D, DD, DD, DD);
    // 5) merged branches: branchcat = xh @ Mcat^T + bfoldcat   [B, 6144]
    gemm_nt<EPI_HB><<<dim3(3 * D / GBN, Bn / GBM), 256, SMEM_GEMM>>>(
        xh, Mh, bfold, nullptr, nullptr, (void*)branch, Bn, 3 * D, D, 0, 0, 0);
    // 6) fused triple LayerNorm -> concat [B, 3D]
    ln3_kernel<<<Bn, 256>>>(x, branch, g[0], bb[0], g[1], bb[1], g[2], bb[2], concat);
    // 7) h1 = relu(concat @ fw1^T + fb1)
    gemm_nt<EPI_HBR><<<dim3(D / GBN, Bn / GBM), 256, SMEM_GEMM>>>(
        concat, fw1h, fb1, nullptr, nullptr, (void*)h1, Bn, D, 3 * D, 0, 0, 0);
    // 8) fused = h1 @ fw2^T + fb2
    gemm_nt<EPI_HB><<<dim3(D / GBN, Bn / GBM), 256, SMEM_GEMM>>>(
        h1, fw2h, fb2, nullptr, nullptr, (void*)fused, Bn, D, D, 0, 0, 0);
    // 9) h2 = relu(fused @ ffw1^T + ffb1)
    gemm_nt<EPI_HBR><<<dim3(4 * D / GBN, Bn / GBM), 256, SMEM_GEMM>>>(
        fused, ffw1h, ffb1, nullptr, nullptr, (void*)h2, Bn, 4 * D, D, 0, 0, 0);
    // 10) out = x + fused + (h2 @ ffw2^T + ffb2)
    gemm_nt<EPI_FINAL><<<dim3(D / GBN, Bn / GBM), 256, SMEM_GEMM>>>(
        h2, ffw2h, ffb2, x, fused, d_out, Bn, D, 4 * D, 0, 0, 0);
}